// round 1
// baseline (speedup 1.0000x reference)
#include <cuda_runtime.h>
#include <math.h>
#include <stdint.h>

// ---------------- problem constants ----------------
#define BATCH   16
#define CIN     12
#define TLEN    16352
#define ATOM    64
#define STRIDE  32
#define NA      128
#define LLEN    512          // latent length
#define NROWS   (BATCH*CIN)  // 192
#define NOUT    (BATCH*CIN*TLEN)  // 3139584

// ---------------- scratch (device globals; no allocation allowed) ----------------
__device__ float g_mean[NROWS];
__device__ float g_std[NROWS];
__device__ float g_istd[NROWS];
__device__ float g_xnorm[(size_t)BATCH*CIN*TLEN];          // 12.5 MB
__device__ float g_h[(size_t)BATCH*LLEN*64];               // [b][l][o]
__device__ float g_zraw[(size_t)BATCH*NA*LLEN];            // 4 MB
__device__ float g_zup[(size_t)BATCH*NA*LLEN];             // 4 MB
__device__ float g_rectotal[(size_t)BATCH*NA*LLEN];        // 4 MB
__device__ float g_w1t[12*64*64];                          // [(c*64+k)][o]
__device__ float g_w2t[64*128];                            // [o][a]
__device__ float g_shpnT[(size_t)NA*ATOM*NA];              // [(ia*64+k)][oa] 4MB
__device__ float g_WdT[(size_t)NA*3*384];                  // [(na*3+m)][row], row=c*32+r
__device__ float g_l1[3];

// ---------------- zero rec_total + l1 accumulators ----------------
__global__ void zero_kernel() {
    int i = blockIdx.x * blockDim.x + threadIdx.x;
    if (i < BATCH*NA*LLEN) g_rectotal[i] = 0.f;
    if (i < 3) g_l1[i] = 0.f;
}

// ---------------- per-row mean/std ----------------
__global__ void stats_kernel(const float* __restrict__ x) {
    int row = blockIdx.x;
    const float* p = x + (size_t)row * TLEN;
    float s = 0.f, s2 = 0.f;
    for (int i = threadIdx.x; i < TLEN; i += 256) {
        float v = p[i]; s += v; s2 += v * v;
    }
    __shared__ float sh[256], sh2[256];
    sh[threadIdx.x] = s; sh2[threadIdx.x] = s2;
    __syncthreads();
    for (int st = 128; st > 0; st >>= 1) {
        if (threadIdx.x < st) { sh[threadIdx.x] += sh[threadIdx.x+st]; sh2[threadIdx.x] += sh2[threadIdx.x+st]; }
        __syncthreads();
    }
    if (threadIdx.x == 0) {
        float mean = sh[0] / (float)TLEN;
        float var  = sh2[0] / (float)TLEN - mean * mean;
        float sd   = sqrtf(var + 1e-5f);
        g_mean[row] = mean; g_std[row] = sd; g_istd[row] = 1.f / sd;
    }
}

__global__ void xnorm_kernel(const float* __restrict__ x) {
    int row = blockIdx.x;
    float mean = g_mean[row], istd = g_istd[row];
    size_t base = (size_t)row * TLEN;
    for (int i = threadIdx.x; i < TLEN; i += 256)
        g_xnorm[base + i] = (x[base + i] - mean) * istd;
}

// ---------------- prep: transposes + shapelet normalize + collapsed decoder W ----------------
__global__ void prep_w1t(const float* __restrict__ w1) {  // w1[o][c][k] -> w1t[(c*64+k)][o]
    int i = blockIdx.x * 256 + threadIdx.x;
    if (i >= 64*768) return;
    int o = i / 768, ck = i % 768;
    g_w1t[ck*64 + o] = w1[i];
}
__global__ void prep_w2t(const float* __restrict__ w2) {  // w2[a][o] -> w2t[o][a]
    int i = blockIdx.x * 256 + threadIdx.x;
    if (i >= 128*64) return;
    int a = i >> 6, o = i & 63;
    g_w2t[o*128 + a] = w2[i];
}
__global__ void prep_shpn(const float* __restrict__ shp) { // normalize per (oa,ia); store [(ia*64+k)][oa]
    int i = blockIdx.x * 256 + threadIdx.x;
    if (i >= NA*NA) return;
    int oa = i >> 7, ia = i & 127;
    const float* p = shp + ((size_t)oa*NA + ia) * ATOM;
    float s = 0.f;
    for (int k = 0; k < ATOM; k++) { float v = p[k]; s += v*v; }
    float nrm = fmaxf(sqrtf(s), 1e-8f);
    float inv = 1.f / nrm;
    for (int k = 0; k < ATOM; k++)
        g_shpnT[((size_t)ia*ATOM + k)*NA + oa] = p[k] * inv;
}
__global__ void prep_WdT(const float* __restrict__ dw) {  // dec_w[c][na][k] collapsed over k-subsets
    int i = blockIdx.x * 256 + threadIdx.x;
    if (i >= 384*NA*3) return;
    int row = i % 384; int rest = i / 384; int m = rest % 3; int na = rest / 3;
    int c = row >> 5, r = row & 31;
    int d = m - 1;
    int klo = 32*d + 31 - r; if (klo < 0) klo = 0;
    int khi = 32*d + 62 - r; if (khi > 63) khi = 63;
    float s = 0.f;
    const float* p = dw + ((size_t)c*NA + na) * ATOM;
    for (int k = klo; k <= khi; k++) s += p[k];
    g_WdT[((size_t)na*3 + m)*384 + row] = s;
}

// ---------------- stem conv: h[b][l][o] = relu(sum_{c,k} w1[o,c,k] xn[b,c,32l-32+k] + b1[o]) ----------------
__global__ __launch_bounds__(128) void stem_kernel(const float* __restrict__ b1) {
    __shared__ float xw[12][576];
    int l0 = blockIdx.x * 16, b = blockIdx.y;
    int tid = threadIdx.x;
    for (int j = tid; j < 12*576; j += 128) {
        int c = j / 576, jj = j % 576;
        int g = 32*l0 - 32 + jj;
        xw[c][jj] = (g >= 0 && g < TLEN) ? g_xnorm[((size_t)b*CIN + c)*TLEN + g] : 0.f;
    }
    __syncthreads();
    int o = tid & 63, lh = tid >> 6;
    float acc[8] = {0,0,0,0,0,0,0,0};
    for (int c = 0; c < 12; c++) {
        #pragma unroll 4
        for (int k = 0; k < 64; k++) {
            float w = g_w1t[(c*64 + k)*64 + o];
            #pragma unroll
            for (int i = 0; i < 8; i++)
                acc[i] += w * xw[c][32*(lh*8 + i) + k];
        }
    }
    float bo = b1[o];
    #pragma unroll
    for (int i = 0; i < 8; i++) {
        int l = l0 + lh*8 + i;
        g_h[((size_t)b*LLEN + l)*64 + o] = fmaxf(acc[i] + bo, 0.f);
    }
}

// ---------------- 1x1: z_raw[b][a][l] = (sum_o w2[a,o] h[b][l][o] + b2[a]) * scale ----------------
__global__ __launch_bounds__(256) void conv1x1_kernel(const float* __restrict__ b2,
                                                      const float* __restrict__ scale) {
    __shared__ float hsm[64][64];     // [l][o]
    __shared__ float w2sm[64][128];   // [o][a]
    int l0 = blockIdx.x * 64, b = blockIdx.y;
    int tid = threadIdx.x;
    for (int i = tid; i < 4096; i += 256) hsm[i >> 6][i & 63] = g_h[((size_t)b*LLEN + l0)*64 + i];
    for (int i = tid; i < 8192; i += 256) w2sm[i >> 7][i & 127] = g_w2t[i];
    __syncthreads();
    int tx = tid & 31, ty = tid >> 5;       // a0=tx*4, l=l0+ty*8+n
    float acc[4][8];
    #pragma unroll
    for (int m = 0; m < 4; m++)
        #pragma unroll
        for (int n = 0; n < 8; n++) acc[m][n] = 0.f;
    for (int o = 0; o < 64; o++) {
        float4 wv = *(const float4*)&w2sm[o][tx*4];
        #pragma unroll
        for (int n = 0; n < 8; n++) {
            float hv = hsm[ty*8 + n][o];
            acc[0][n] += wv.x * hv; acc[1][n] += wv.y * hv;
            acc[2][n] += wv.z * hv; acc[3][n] += wv.w * hv;
        }
    }
    float sc = scale[0];
    #pragma unroll
    for (int m = 0; m < 4; m++) {
        int a = tx*4 + m;
        float bb = b2[a];
        #pragma unroll
        for (int n = 0; n < 8; n++)
            g_zraw[((size_t)b*NA + a)*LLEN + l0 + ty*8 + n] = (acc[m][n] + bb) * sc;
    }
}

// ---------------- pool: residual -> z_q (avg s) -> |.| sum -> z_up (repeat s) ----------------
__global__ __launch_bounds__(128) void pool_kernel(int s, int idx) {
    int row = blockIdx.x;                 // b*128+a
    size_t base = (size_t)row * LLEN;
    int nq = LLEN / s;
    float inv = 1.f / (float)s;
    float local = 0.f;
    for (int j = threadIdx.x; j < nq; j += 128) {
        int t0 = j * s;
        float sum = 0.f;
        for (int t = 0; t < s; t++) sum += g_zraw[base + t0 + t] - g_rectotal[base + t0 + t];
        float zq = sum * inv;
        local += fabsf(zq);
        for (int t = 0; t < s; t++) g_zup[base + t0 + t] = zq;
    }
    __shared__ float red[128];
    red[threadIdx.x] = local;
    __syncthreads();
    for (int st = 64; st > 0; st >>= 1) {
        if (threadIdx.x < st) red[threadIdx.x] += red[threadIdx.x + st];
        __syncthreads();
    }
    if (threadIdx.x == 0) atomicAdd(&g_l1[idx], red[0]);
}

// ---------------- shapelet conv: rec_total[b,oa,t] += sum_{ia,k} shpn[oa,ia,k] zup[b,ia,t-31+k] ----------------
// grid: (4 t-tiles, 4 = oa_half*ia_half, 16 b); block tile: 64 oa x 128 t, K-half = 64 ia
__global__ __launch_bounds__(256) void conv_scale_kernel() {
    __shared__ float Wsm[64][64];  // [k][oa_local]
    __shared__ float zsm[192];
    int t0 = blockIdx.x * 128;
    int oa_half = blockIdx.y & 1, ia_half = blockIdx.y >> 1;
    int b = blockIdx.z;
    int tid = threadIdx.x;
    int tx = tid & 15, ty = tid >> 4;   // oa0=oa_half*64+tx*4, t=t0+ty*8+n
    float acc[4][8];
    #pragma unroll
    for (int m = 0; m < 4; m++)
        #pragma unroll
        for (int n = 0; n < 8; n++) acc[m][n] = 0.f;

    const float* zupb = g_zup + ((size_t)b*NA + ia_half*64) * LLEN;
    for (int ial = 0; ial < 64; ial++) {
        __syncthreads();
        int ia = ia_half*64 + ial;
        const float* wp = g_shpnT + ((size_t)ia*ATOM)*NA + oa_half*64;
        #pragma unroll
        for (int i = 0; i < 16; i++) {
            int idx = tid + i*256;
            int k = idx >> 6, ol = idx & 63;
            Wsm[k][ol] = wp[(size_t)k*NA + ol];
        }
        if (tid < 192) {
            int tg = t0 - 31 + tid;
            zsm[tid] = (tg >= 0 && tg < LLEN) ? zupb[(size_t)ial*LLEN + tg] : 0.f;
        }
        __syncthreads();
        float z[8];
        #pragma unroll
        for (int n = 0; n < 8; n++) z[n] = zsm[ty*8 + n];
        #pragma unroll 8
        for (int k = 0; k < 64; k++) {
            float4 wv = *(const float4*)&Wsm[k][tx*4];
            #pragma unroll
            for (int n = 0; n < 8; n++) {
                acc[0][n] += wv.x * z[n]; acc[1][n] += wv.y * z[n];
                acc[2][n] += wv.z * z[n]; acc[3][n] += wv.w * z[n];
            }
            #pragma unroll
            for (int n = 0; n < 7; n++) z[n] = z[n+1];
            z[7] = zsm[ty*8 + k + 8];
        }
    }
    int oa = oa_half*64 + tx*4;
    #pragma unroll
    for (int m = 0; m < 4; m++)
        #pragma unroll
        for (int n = 0; n < 8; n++)
            atomicAdd(&g_rectotal[((size_t)b*NA + oa + m)*LLEN + t0 + ty*8 + n], acc[m][n]);
}

// ---------------- decoder: collapsed K=3 conv + affine + slice, writes recon ----------------
// rows = c*32+r (384), out[b,c,32q+r] for q<511
__global__ __launch_bounds__(256) void decoder_kernel(const float* __restrict__ dec_b,
                                                      float* __restrict__ out) {
    __shared__ float Wsm[4][3][64];
    __shared__ float zsm[4][130];
    int q0 = blockIdx.x * 128;
    int row0 = blockIdx.y * 64;
    int b = blockIdx.z;
    int tid = threadIdx.x, tx = tid & 15, ty = tid >> 4;
    float acc[4][8];
    #pragma unroll
    for (int m = 0; m < 4; m++)
        #pragma unroll
        for (int n = 0; n < 8; n++) acc[m][n] = 0.f;

    for (int na0 = 0; na0 < NA; na0 += 4) {
        __syncthreads();
        for (int i = tid; i < 768; i += 256) {
            int nl = i / 192, rem = i % 192, m = rem / 64, rl = rem % 64;
            Wsm[nl][m][rl] = g_WdT[((size_t)(na0+nl)*3 + m)*384 + row0 + rl];
        }
        for (int i = tid; i < 520; i += 256) {
            int nl = i / 130, j = i % 130;
            int q = q0 - 1 + j;
            zsm[nl][j] = (q >= 0 && q < LLEN) ? g_rectotal[((size_t)b*NA + na0 + nl)*LLEN + q] : 0.f;
        }
        __syncthreads();
        #pragma unroll
        for (int nl = 0; nl < 4; nl++) {
            float z[10];
            #pragma unroll
            for (int j = 0; j < 10; j++) z[j] = zsm[nl][ty*8 + j];
            #pragma unroll
            for (int m = 0; m < 3; m++) {
                float4 wv = *(const float4*)&Wsm[nl][m][tx*4];
                #pragma unroll
                for (int n = 0; n < 8; n++) {
                    float zz = z[n + m];
                    acc[0][n] += wv.x * zz; acc[1][n] += wv.y * zz;
                    acc[2][n] += wv.z * zz; acc[3][n] += wv.w * zz;
                }
            }
        }
    }
    int row = row0 + tx*4;          // 4 consecutive r, same c
    int c = row >> 5, r0 = row & 31;
    float sd = g_std[b*CIN + c], mn = g_mean[b*CIN + c], bb = dec_b[c];
    float* ob = out + ((size_t)(b*CIN + c)) * TLEN;
    #pragma unroll
    for (int n = 0; n < 8; n++) {
        int q = q0 + ty*8 + n;
        if (q < 511) {
            float4 v;
            v.x = (acc[0][n] + bb) * sd + mn;
            v.y = (acc[1][n] + bb) * sd + mn;
            v.z = (acc[2][n] + bb) * sd + mn;
            v.w = (acc[3][n] + bb) * sd + mn;
            *(float4*)&ob[q*32 + r0] = v;
        }
    }
}

// ---------------- scalars ----------------
__global__ void finalize_kernel(float* __restrict__ out) {
    out[NOUT]     = 0.f;
    out[NOUT + 1] = 0.01f * (g_l1[0] / (16.f*128.f*128.f)
                           + g_l1[1] / (16.f*128.f*256.f)
                           + g_l1[2] / (16.f*128.f*512.f));
}

// ---------------- launch ----------------
extern "C" void kernel_launch(void* const* d_in, const int* in_sizes, int n_in,
                              void* d_out, int out_size) {
    const float* x     = (const float*)d_in[0];
    const float* w1    = (const float*)d_in[1];
    const float* b1    = (const float*)d_in[2];
    const float* w2    = (const float*)d_in[3];
    const float* b2    = (const float*)d_in[4];
    const float* scl   = (const float*)d_in[5];
    const float* shp   = (const float*)d_in[6];
    const float* dw    = (const float*)d_in[7];
    const float* db    = (const float*)d_in[8];
    float* out = (float*)d_out;

    zero_kernel<<<(BATCH*NA*LLEN + 511)/512, 512>>>();
    stats_kernel<<<NROWS, 256>>>(x);
    xnorm_kernel<<<NROWS, 256>>>(x);

    prep_w1t<<<(64*768 + 255)/256, 256>>>(w1);
    prep_w2t<<<(128*64 + 255)/256, 256>>>(w2);
    prep_shpn<<<(NA*NA + 255)/256, 256>>>(shp);
    prep_WdT<<<(384*NA*3 + 255)/256, 256>>>(dw);

    stem_kernel<<<dim3(32, BATCH), 128>>>(b1);
    conv1x1_kernel<<<dim3(8, BATCH), 256>>>(b2, scl);

    const int scales[3] = {4, 2, 1};
    for (int si = 0; si < 3; si++) {
        pool_kernel<<<BATCH*NA, 128>>>(scales[si], si);
        conv_scale_kernel<<<dim3(4, 4, BATCH), 256>>>();
    }

    decoder_kernel<<<dim3(4, 6, BATCH), 256>>>(db, out);
    if (out_size >= NOUT + 2) finalize_kernel<<<1, 1>>>(out);
}

// round 4
// speedup vs baseline: 1.2156x; 1.2156x over previous
#include <cuda_runtime.h>
#include <math.h>
#include <stdint.h>

// ---------------- problem constants ----------------
#define BATCH   16
#define CIN     12
#define TLEN    16352
#define ATOM    64
#define STRIDE  32
#define NA      128
#define LLEN    512
#define NROWS   (BATCH*CIN)
#define NOUT    (BATCH*CIN*TLEN)

// ---------------- scratch (device globals) ----------------
__device__ float g_mean[NROWS];
__device__ float g_std[NROWS];
__device__ float g_istd[NROWS];
__device__ float g_xnorm[(size_t)BATCH*CIN*TLEN];
__device__ float g_h[(size_t)BATCH*LLEN*64];
__device__ float g_zraw[(size_t)BATCH*NA*LLEN];
__device__ float g_zq[(size_t)BATCH*NA*LLEN];          // compact z_q, stride 512/row, first LQ valid
__device__ float g_rectotal[(size_t)BATCH*NA*LLEN];
__device__ float g_w1t[12*64*64];
__device__ float g_w2t[64*128];
__device__ float g_shpnT[(size_t)NA*ATOM*NA];          // [(ia*64+k)*128 + oa]  (== Wc for s=1)
__device__ float g_Wc4[(size_t)4*128*17*128];          // [((r*128+ia)*17+mc)*128+oa]
__device__ float g_Wc2[(size_t)2*128*33*128];          // [((r*128+ia)*33+mc)*128+oa]
__device__ float g_WdT[(size_t)NA*3*384];
__device__ float g_l1[3];

// compile-time weight selector (avoids host cudaGetSymbolAddress)
template<int SEL> __device__ __forceinline__ const float* wc_ptr();
template<> __device__ __forceinline__ const float* wc_ptr<4>() { return g_Wc4; }
template<> __device__ __forceinline__ const float* wc_ptr<2>() { return g_Wc2; }
template<> __device__ __forceinline__ const float* wc_ptr<1>() { return g_shpnT; }

// ---------------- zero ----------------
__global__ void zero_kernel() {
    int i = blockIdx.x * blockDim.x + threadIdx.x;
    if (i < BATCH*NA*LLEN) g_rectotal[i] = 0.f;
    if (i < 3) g_l1[i] = 0.f;
}

// ---------------- per-row mean/std ----------------
__global__ void stats_kernel(const float* __restrict__ x) {
    int row = blockIdx.x;
    const float* p = x + (size_t)row * TLEN;
    float s = 0.f, s2 = 0.f;
    for (int i = threadIdx.x; i < TLEN; i += 256) { float v = p[i]; s += v; s2 += v*v; }
    __shared__ float sh[256], sh2[256];
    sh[threadIdx.x] = s; sh2[threadIdx.x] = s2;
    __syncthreads();
    for (int st = 128; st > 0; st >>= 1) {
        if (threadIdx.x < st) { sh[threadIdx.x] += sh[threadIdx.x+st]; sh2[threadIdx.x] += sh2[threadIdx.x+st]; }
        __syncthreads();
    }
    if (threadIdx.x == 0) {
        float mean = sh[0] / (float)TLEN;
        float var  = sh2[0] / (float)TLEN - mean * mean;
        float sd   = sqrtf(var + 1e-5f);
        g_mean[row] = mean; g_std[row] = sd; g_istd[row] = 1.f / sd;
    }
}

__global__ void xnorm_kernel(const float* __restrict__ x) {
    int row = blockIdx.x;
    float mean = g_mean[row], istd = g_istd[row];
    size_t base = (size_t)row * TLEN;
    for (int i = threadIdx.x; i < TLEN; i += 256)
        g_xnorm[base + i] = (x[base + i] - mean) * istd;
}

// ---------------- prep ----------------
__global__ void prep_w1t(const float* __restrict__ w1) {
    int i = blockIdx.x * 256 + threadIdx.x;
    if (i >= 64*768) return;
    int o = i / 768, ck = i % 768;
    g_w1t[ck*64 + o] = w1[i];
}
__global__ void prep_w2t(const float* __restrict__ w2) {
    int i = blockIdx.x * 256 + threadIdx.x;
    if (i >= 128*64) return;
    int a = i >> 6, o = i & 63;
    g_w2t[o*128 + a] = w2[i];
}
__global__ void prep_shpn(const float* __restrict__ shp) {
    int i = blockIdx.x * 256 + threadIdx.x;
    if (i >= NA*NA) return;
    int oa = i >> 7, ia = i & 127;
    const float* p = shp + ((size_t)oa*NA + ia) * ATOM;
    float s = 0.f;
    for (int k = 0; k < ATOM; k++) { float v = p[k]; s += v*v; }
    float inv = 1.f / fmaxf(sqrtf(s), 1e-8f);
    for (int k = 0; k < ATOM; k++)
        g_shpnT[((size_t)ia*ATOM + k)*NA + oa] = p[k] * inv;
}
// collapsed per-residue weights: Wc[r][ia][mc][oa] = sum_{k: floor((r-31+k)/S)=mc-MLO} shpn[oa,ia,k]
template<int S, int KC, int MLO>
__global__ void prep_Wc() {
    float* gW = (S == 4) ? g_Wc4 : g_Wc2;
    const int total = S * 128 * KC * 128;
    int i = blockIdx.x * 256 + threadIdx.x;
    if (i >= total) return;
    int oa = i & 127;
    int rest = i >> 7;
    int mc = rest % KC;
    int rest2 = rest / KC;
    int ia = rest2 & 127;
    int r  = rest2 >> 7;
    int m = mc - MLO;
    int klo = S*m + 31 - r;
    int khi = klo + S - 1;
    if (klo < 0) klo = 0;
    if (khi > 63) khi = 63;
    float s = 0.f;
    for (int k = klo; k <= khi; k++)
        s += g_shpnT[((size_t)ia*ATOM + k)*NA + oa];
    gW[i] = s;
}
__global__ void prep_WdT(const float* __restrict__ dw) {
    int i = blockIdx.x * 256 + threadIdx.x;
    if (i >= 384*NA*3) return;
    int row = i % 384; int rest = i / 384; int m = rest % 3; int na = rest / 3;
    int c = row >> 5, r = row & 31;
    int d = m - 1;
    int klo = 32*d + 31 - r; if (klo < 0) klo = 0;
    int khi = 32*d + 62 - r; if (khi > 63) khi = 63;
    float s = 0.f;
    const float* p = dw + ((size_t)c*NA + na) * ATOM;
    for (int k = klo; k <= khi; k++) s += p[k];
    g_WdT[((size_t)na*3 + m)*384 + row] = s;
}

// ---------------- stem ----------------
__global__ __launch_bounds__(128) void stem_kernel(const float* __restrict__ b1) {
    __shared__ float xw[12][576];
    int l0 = blockIdx.x * 16, b = blockIdx.y;
    int tid = threadIdx.x;
    for (int j = tid; j < 12*576; j += 128) {
        int c = j / 576, jj = j % 576;
        int g = 32*l0 - 32 + jj;
        xw[c][jj] = (g >= 0 && g < TLEN) ? g_xnorm[((size_t)b*CIN + c)*TLEN + g] : 0.f;
    }
    __syncthreads();
    int o = tid & 63, lh = tid >> 6;
    float acc[8] = {0,0,0,0,0,0,0,0};
    for (int c = 0; c < 12; c++) {
        #pragma unroll 4
        for (int k = 0; k < 64; k++) {
            float w = g_w1t[(c*64 + k)*64 + o];
            #pragma unroll
            for (int i = 0; i < 8; i++)
                acc[i] += w * xw[c][32*(lh*8 + i) + k];
        }
    }
    float bo = b1[o];
    #pragma unroll
    for (int i = 0; i < 8; i++) {
        int l = l0 + lh*8 + i;
        g_h[((size_t)b*LLEN + l)*64 + o] = fmaxf(acc[i] + bo, 0.f);
    }
}

// ---------------- 1x1 ----------------
__global__ __launch_bounds__(256) void conv1x1_kernel(const float* __restrict__ b2,
                                                      const float* __restrict__ scale) {
    __shared__ float hsm[64][64];
    __shared__ float w2sm[64][128];
    int l0 = blockIdx.x * 64, b = blockIdx.y;
    int tid = threadIdx.x;
    for (int i = tid; i < 4096; i += 256) hsm[i >> 6][i & 63] = g_h[((size_t)b*LLEN + l0)*64 + i];
    for (int i = tid; i < 8192; i += 256) w2sm[i >> 7][i & 127] = g_w2t[i];
    __syncthreads();
    int tx = tid & 31, ty = tid >> 5;
    float acc[4][8];
    #pragma unroll
    for (int m = 0; m < 4; m++)
        #pragma unroll
        for (int n = 0; n < 8; n++) acc[m][n] = 0.f;
    for (int o = 0; o < 64; o++) {
        float4 wv = *(const float4*)&w2sm[o][tx*4];
        #pragma unroll
        for (int n = 0; n < 8; n++) {
            float hv = hsm[ty*8 + n][o];
            acc[0][n] += wv.x * hv; acc[1][n] += wv.y * hv;
            acc[2][n] += wv.z * hv; acc[3][n] += wv.w * hv;
        }
    }
    float sc = scale[0];
    #pragma unroll
    for (int m = 0; m < 4; m++) {
        int a = tx*4 + m;
        float bb = b2[a];
        #pragma unroll
        for (int n = 0; n < 8; n++)
            g_zraw[((size_t)b*NA + a)*LLEN + l0 + ty*8 + n] = (acc[m][n] + bb) * sc;
    }
}

// ---------------- pool: residual -> compact z_q + l1 ----------------
__global__ __launch_bounds__(128) void pool_kernel(int s, int idx) {
    int row = blockIdx.x;                 // b*128 + a
    size_t base = (size_t)row * LLEN;
    int nq = LLEN / s;
    float inv = 1.f / (float)s;
    float local = 0.f;
    for (int j = threadIdx.x; j < nq; j += 128) {
        int t0 = j * s;
        float sum = 0.f;
        for (int t = 0; t < s; t++) sum += g_zraw[base + t0 + t] - g_rectotal[base + t0 + t];
        float zq = sum * inv;
        local += fabsf(zq);
        g_zq[base + j] = zq;
    }
    __shared__ float red[128];
    red[threadIdx.x] = local;
    __syncthreads();
    for (int st = 64; st > 0; st >>= 1) {
        if (threadIdx.x < st) red[threadIdx.x] += red[threadIdx.x + st];
        __syncthreads();
    }
    if (threadIdx.x == 0) atomicAdd(&g_l1[idx], red[0]);
}

// ---------------- collapsed shapelet conv ----------------
// rec_total[b, oa, S*u + r] += sum_{ia, mc} Wc[r][ia][mc][oa] * z_q[b, ia, u + mc - MLO]
// grid (4 = utile*S+r, 4 = ia_half*2+oa_half, 16 b); block: 64 oa x 128 u outputs
template<int KC, int S, int MLO>
__global__ __launch_bounds__(256) void conv_collapsed_kernel() {
    const float* gW = wc_ptr<S>();
    __shared__ float Wsm[KC][64];
    __shared__ float zsm[192 + 8];
    const int LQ = LLEN / S;
    int r = blockIdx.x % S;
    int u0 = (blockIdx.x / S) * 128;
    int oa_half = blockIdx.y & 1, ia_half = blockIdx.y >> 1;
    int b = blockIdx.z;
    int tid = threadIdx.x;
    int tx = tid & 15, ty = tid >> 4;   // oa0 = oa_half*64 + tx*4, u = u0 + ty*8 + n
    float acc[4][8];
    #pragma unroll
    for (int m = 0; m < 4; m++)
        #pragma unroll
        for (int n = 0; n < 8; n++) acc[m][n] = 0.f;

    const float* zrow = g_zq + ((size_t)b*NA + ia_half*64) * LLEN;
    for (int ial = 0; ial < 64; ial++) {
        __syncthreads();
        int ia = ia_half*64 + ial;
        const float* wp = gW + (((size_t)r*128 + ia)*KC)*128 + oa_half*64;
        for (int i = tid; i < KC*64; i += 256) {
            int mc = i >> 6, ol = i & 63;
            Wsm[mc][ol] = wp[(size_t)mc*128 + ol];
        }
        for (int j = tid; j < 128 + KC - 1; j += 256) {
            int uq = u0 - MLO + j;
            zsm[j] = (uq >= 0 && uq < LQ) ? zrow[(size_t)ial*LLEN + uq] : 0.f;
        }
        __syncthreads();
        float z[8];
        #pragma unroll
        for (int n = 0; n < 8; n++) z[n] = zsm[ty*8 + n];
        #pragma unroll 8
        for (int mc = 0; mc < KC; mc++) {
            float4 wv = *(const float4*)&Wsm[mc][tx*4];
            #pragma unroll
            for (int n = 0; n < 8; n++) {
                acc[0][n] += wv.x * z[n]; acc[1][n] += wv.y * z[n];
                acc[2][n] += wv.z * z[n]; acc[3][n] += wv.w * z[n];
            }
            #pragma unroll
            for (int n = 0; n < 7; n++) z[n] = z[n+1];
            z[7] = zsm[ty*8 + mc + 8];
        }
    }
    int oa = oa_half*64 + tx*4;
    #pragma unroll
    for (int m = 0; m < 4; m++) {
        float* dst = g_rectotal + ((size_t)b*NA + oa + m)*LLEN + r;
        #pragma unroll
        for (int n = 0; n < 8; n++)
            atomicAdd(&dst[(size_t)S*(u0 + ty*8 + n)], acc[m][n]);
    }
}

// ---------------- decoder ----------------
__global__ __launch_bounds__(256) void decoder_kernel(const float* __restrict__ dec_b,
                                                      float* __restrict__ out) {
    __shared__ float Wsm[4][3][64];
    __shared__ float zsm[4][130];
    int q0 = blockIdx.x * 128;
    int row0 = blockIdx.y * 64;
    int b = blockIdx.z;
    int tid = threadIdx.x, tx = tid & 15, ty = tid >> 4;
    float acc[4][8];
    #pragma unroll
    for (int m = 0; m < 4; m++)
        #pragma unroll
        for (int n = 0; n < 8; n++) acc[m][n] = 0.f;

    for (int na0 = 0; na0 < NA; na0 += 4) {
        __syncthreads();
        for (int i = tid; i < 768; i += 256) {
            int nl = i / 192, rem = i % 192, m = rem / 64, rl = rem % 64;
            Wsm[nl][m][rl] = g_WdT[((size_t)(na0+nl)*3 + m)*384 + row0 + rl];
        }
        for (int i = tid; i < 520; i += 256) {
            int nl = i / 130, j = i % 130;
            int q = q0 - 1 + j;
            zsm[nl][j] = (q >= 0 && q < LLEN) ? g_rectotal[((size_t)b*NA + na0 + nl)*LLEN + q] : 0.f;
        }
        __syncthreads();
        #pragma unroll
        for (int nl = 0; nl < 4; nl++) {
            float z[10];
            #pragma unroll
            for (int j = 0; j < 10; j++) z[j] = zsm[nl][ty*8 + j];
            #pragma unroll
            for (int m = 0; m < 3; m++) {
                float4 wv = *(const float4*)&Wsm[nl][m][tx*4];
                #pragma unroll
                for (int n = 0; n < 8; n++) {
                    float zz = z[n + m];
                    acc[0][n] += wv.x * zz; acc[1][n] += wv.y * zz;
                    acc[2][n] += wv.z * zz; acc[3][n] += wv.w * zz;
                }
            }
        }
    }
    int row = row0 + tx*4;
    int c = row >> 5, r0 = row & 31;
    float sd = g_std[b*CIN + c], mn = g_mean[b*CIN + c], bb = dec_b[c];
    float* ob = out + ((size_t)(b*CIN + c)) * TLEN;
    #pragma unroll
    for (int n = 0; n < 8; n++) {
        int q = q0 + ty*8 + n;
        if (q < 511) {
            float4 v;
            v.x = (acc[0][n] + bb) * sd + mn;
            v.y = (acc[1][n] + bb) * sd + mn;
            v.z = (acc[2][n] + bb) * sd + mn;
            v.w = (acc[3][n] + bb) * sd + mn;
            *(float4*)&ob[q*32 + r0] = v;
        }
    }
}

__global__ void finalize_kernel(float* __restrict__ out) {
    out[NOUT]     = 0.f;
    out[NOUT + 1] = 0.01f * (g_l1[0] / (16.f*128.f*128.f)
                           + g_l1[1] / (16.f*128.f*256.f)
                           + g_l1[2] / (16.f*128.f*512.f));
}

// ---------------- launch ----------------
extern "C" void kernel_launch(void* const* d_in, const int* in_sizes, int n_in,
                              void* d_out, int out_size) {
    const float* x   = (const float*)d_in[0];
    const float* w1  = (const float*)d_in[1];
    const float* b1  = (const float*)d_in[2];
    const float* w2  = (const float*)d_in[3];
    const float* b2  = (const float*)d_in[4];
    const float* scl = (const float*)d_in[5];
    const float* shp = (const float*)d_in[6];
    const float* dw  = (const float*)d_in[7];
    const float* db  = (const float*)d_in[8];
    float* out = (float*)d_out;

    zero_kernel<<<(BATCH*NA*LLEN + 511)/512, 512>>>();
    stats_kernel<<<NROWS, 256>>>(x);
    xnorm_kernel<<<NROWS, 256>>>(x);

    prep_w1t<<<(64*768 + 255)/256, 256>>>(w1);
    prep_w2t<<<(128*64 + 255)/256, 256>>>(w2);
    prep_shpn<<<(NA*NA + 255)/256, 256>>>(shp);
    prep_WdT<<<(384*NA*3 + 255)/256, 256>>>(dw);

    prep_Wc<4, 17, 8><<<(4*128*17*128 + 255)/256, 256>>>();
    prep_Wc<2, 33, 16><<<(2*128*33*128 + 255)/256, 256>>>();

    stem_kernel<<<dim3(32, BATCH), 128>>>(b1);
    conv1x1_kernel<<<dim3(8, BATCH), 256>>>(b2, scl);

    // scale 4
    pool_kernel<<<BATCH*NA, 128>>>(4, 0);
    conv_collapsed_kernel<17, 4, 8><<<dim3(4, 4, BATCH), 256>>>();
    // scale 2
    pool_kernel<<<BATCH*NA, 128>>>(2, 1);
    conv_collapsed_kernel<33, 2, 16><<<dim3(4, 4, BATCH), 256>>>();
    // scale 1
    pool_kernel<<<BATCH*NA, 128>>>(1, 2);
    conv_collapsed_kernel<64, 1, 31><<<dim3(4, 4, BATCH), 256>>>();

    decoder_kernel<<<dim3(4, 6, BATCH), 256>>>(db, out);
    if (out_size >= NOUT + 2) finalize_kernel<<<1, 1>>>(out);
}